// round 17
// baseline (speedup 1.0000x reference)
#include <cuda_runtime.h>
#include <cuda_fp16.h>
#include <math.h>
#include <stdint.h>

#define BB 32
#define CC 64
#define TT_ 128
#define VV 25
#define RR 8
#define TS 9
#define OUTC 64
#define TV 3200    // TT_*VV
#define TVP 3328   // TT_*26 (padded z row)

// scratch (allocation-free rule: device globals)
__device__ float g_xm[BB * CC * VV];                   // mean_t x
__device__ float g_dbuf[BB * RR * VV * VV];            // d[b,r,j,i]
__device__ __half g_zh[(size_t)BB * CC * TVP];         // z[b,c,t*26+i] fp16

__device__ __forceinline__ uint32_t smem_to_u32(const void* smem_ptr) {
    uint32_t addr;
    asm("{ .reg .u64 tmp; cvta.to.shared.u64 tmp, %1; cvt.u32.u64 %0, tmp; }" : "=r"(addr) : "l"(smem_ptr));
    return addr;
}
#define SMEM_SWIZZLE_128B(byte_offset) ((byte_offset) ^ (((byte_offset) >> 3) & 0x70))

__device__ __forceinline__ void ldsm_x4(uint32_t* r, uint32_t addr) {
    asm volatile("ldmatrix.sync.aligned.m8n8.x4.shared.b16 {%0,%1,%2,%3}, [%4];"
                 : "=r"(r[0]), "=r"(r[1]), "=r"(r[2]), "=r"(r[3]) : "r"(addr));
}
__device__ __forceinline__ void mma_16816_f16(float* d, const uint32_t* a, uint32_t b0, uint32_t b1) {
    asm volatile(
        "mma.sync.aligned.m16n8k16.row.col.f32.f16.f16.f32 "
        "{%0,%1,%2,%3}, {%4,%5,%6,%7}, {%8,%9}, {%0,%1,%2,%3};"
        : "+f"(d[0]), "+f"(d[1]), "+f"(d[2]), "+f"(d[3])
        : "r"(a[0]), "r"(a[1]), "r"(a[2]), "r"(a[3]), "r"(b0), "r"(b1));
}
__device__ __forceinline__ uint32_t pack_h2f(float a, float b) {
    __half2 h = __floats2half2_rn(a, b);
    return *reinterpret_cast<uint32_t*>(&h);
}

// ---------------- kA1: coalesced mean over T, one block per (b,c) ----------------
__global__ void __launch_bounds__(128) kA1(const float* __restrict__ x) {
    int c = blockIdx.x, b = blockIdx.y;
    int tid = threadIdx.x;
    __shared__ float xt[TT_ * VV];
    __shared__ float part[VV * 4];

    const float* xp = x + (size_t)(b * CC + c) * TV;
    for (int i = tid; i < TT_ * VV; i += 128) xt[i] = xp[i];
    __syncthreads();

    if (tid < VV * 4) {
        int v = tid >> 2, s = tid & 3;
        float acc = 0.f;
#pragma unroll 8
        for (int t = s; t < TT_; t += 4) acc += xt[t * VV + v];
        part[tid] = acc;
    }
    __syncthreads();
    if (tid < VV) {
        float m = (part[tid * 4] + part[tid * 4 + 1] + part[tid * 4 + 2] + part[tid * 4 + 3]) * (1.f / (float)TT_);
        g_xm[(b * CC + c) * VV + tid] = m;
    }
}

// ---------------- kA2: x1/x2 + d = tanh(x1-x2), one block per (r, b) ----------------
__global__ void __launch_bounds__(128) kA2(const float* __restrict__ w1, const float* __restrict__ b1,
                                           const float* __restrict__ w2, const float* __restrict__ b2) {
    int r = blockIdx.x;
    int b = blockIdx.y;
    int tid = threadIdx.x;
    __shared__ float xm[CC * VV];
    __shared__ float x1s[VV];
    __shared__ float x2s[VV];

    const float* xmg = g_xm + b * (CC * VV);
    for (int i = tid; i < CC * VV; i += 128) xm[i] = xmg[i];
    __syncthreads();

    if (tid < 2 * VV) {
        int which = tid / VV;
        int v = tid % VV;
        const float* w = which ? w2 : w1;
        float s = 0.f;
#pragma unroll 8
        for (int c = 0; c < CC; c++) s = fmaf(w[r * CC + c], xm[c * VV + v], s);
        s += (which ? b2 : b1)[r];
        (which ? x2s : x1s)[v] = s;
    }
    __syncthreads();

    float* db = g_dbuf + (b * RR + r) * (VV * VV);
    for (int p = tid; p < VV * VV; p += 128) {
        int j = p / VV, i = p % VV;
        db[p] = tanhf(x1s[j] - x2s[i]);
    }
}

// ---------------- kB_mma: dynamic conv, 512 threads, warp-pair np split ----------------
// Warps (g, g+8) share t-tile [g*16, g*16+16); warp g does i 0-15 (np=0), g+8 does i 16-31.
#define KB_A_ROW 80
#define KB_A_BYTES (136 * KB_A_ROW)           // 10880
#define KB_B_GRP (32 * KB_A_ROW)              // 2560
#define KB_B_BYTES (TS * KB_B_GRP)            // 23040

__global__ void __launch_bounds__(512) kB_mma(const float* __restrict__ x,
                                              const float* __restrict__ Amat,
                                              const float* __restrict__ w4, const float* __restrict__ b4) {
    __shared__ __align__(16) char sA[KB_A_BYTES];
    __shared__ __align__(16) char sB[KB_B_BYTES];
    __shared__ __align__(16) float4 w4s4[TS * 2];
    __shared__ float b4s[TS];

    int c = blockIdx.x;
    int b = blockIdx.y;
    int tid = threadIdx.x;
    int warp = tid >> 5, lane = tid & 31;

    // phase 0: zero smem tiles + stage w4/b4
    {
        uint4 z4 = make_uint4(0, 0, 0, 0);
        uint4* pa = reinterpret_cast<uint4*>(sA);
        for (int i = tid; i < KB_A_BYTES / 16; i += 512) pa[i] = z4;
        uint4* pb = reinterpret_cast<uint4*>(sB);
        for (int i = tid; i < KB_B_BYTES / 16; i += 512) pb[i] = z4;
    }
    if (tid < TS * 2) {
        int k = tid >> 1, h = tid & 1;
        w4s4[tid] = *reinterpret_cast<const float4*>(w4 + (size_t)(c * TS + k) * RR + h * 4);
    }
    if (tid < TS) b4s[tid] = b4[c * TS + tid];
    __syncthreads();

    // ---- build W -> B tiles [k][i][j] fp16 ----
    const float* db = g_dbuf + b * (RR * VV * VV);
    for (int p = tid; p < VV * VV; p += 512) {
        float dr[RR];
#pragma unroll
        for (int r = 0; r < RR; r++) dr[r] = __ldg(db + r * (VV * VV) + p);
        float a = __ldg(Amat + p);
        int j = p / VV, i = p % VV;
#pragma unroll
        for (int k = 0; k < TS; k++) {
            float4 wa = w4s4[2 * k], wb = w4s4[2 * k + 1];
            float s = a + b4s[k];
            s = fmaf(wa.x, dr[0], s); s = fmaf(wa.y, dr[1], s);
            s = fmaf(wa.z, dr[2], s); s = fmaf(wa.w, dr[3], s);
            s = fmaf(wb.x, dr[4], s); s = fmaf(wb.y, dr[5], s);
            s = fmaf(wb.z, dr[6], s); s = fmaf(wb.w, dr[7], s);
            *reinterpret_cast<__half*>(sB + (uint32_t)k * KB_B_GRP + (uint32_t)i * KB_A_ROW + (uint32_t)j * 2u) =
                __float2half_rn(s);
        }
    }

    // ---- stage xpad: A[s=t+8][j] = x[t][j] fp16 ----
    const float* xp = x + (size_t)(b * CC + c) * TV;
    for (int idx = tid; idx < TT_ * VV; idx += 512) {
        int t = idx / VV, j = idx % VV;
        *reinterpret_cast<__half*>(sA + (uint32_t)(t + 8) * KB_A_ROW + (uint32_t)j * 2u) =
            __float2half_rn(xp[idx]);
    }
    __syncthreads();

    uint32_t aH = smem_to_u32(sA);
    uint32_t bH = smem_to_u32(sB);

    float acc[2][4];
#pragma unroll
    for (int n = 0; n < 2; n++)
#pragma unroll
        for (int q = 0; q < 4; q++) acc[n][q] = 0.f;

    int g = warp & 7;           // t-tile
    int nh = warp >> 3;         // i-half (0: i 0-15, 1: i 16-31)
    int t0 = g * 16;
    uint32_t a_lane = (uint32_t)(lane & 15) * KB_A_ROW + (uint32_t)((lane >> 4) & 1) * 16u;
    uint32_t b_lane = (uint32_t)(((lane >> 4) & 1) * 8 + (lane & 7)) * KB_A_ROW
                    + (uint32_t)((lane >> 3) & 1) * 16u;
    uint32_t b_half = (uint32_t)nh * 16u * KB_A_ROW;

#pragma unroll
    for (int k = 0; k < TS; k++) {
        uint32_t a_base = (uint32_t)(k + t0) * KB_A_ROW + a_lane;
        uint32_t b_base = (uint32_t)k * KB_B_GRP + b_half + b_lane;
#pragma unroll
        for (int ks = 0; ks < 2; ks++) {
            uint32_t ah[4];
            ldsm_x4(ah, aH + a_base + (uint32_t)ks * 32u);
            uint32_t bh[4];
            ldsm_x4(bh, bH + b_base + (uint32_t)ks * 32u);
            mma_16816_f16(acc[0], ah, bh[0], bh[1]);
            mma_16816_f16(acc[1], ah, bh[2], bh[3]);
        }
    }

    // ---- epilogue: D frag -> z fp16 [t*26 + i] ----
    int tr = lane >> 2, cq = (lane & 3) * 2;
    __half* zp = g_zh + (size_t)(b * CC + c) * TVP;
    int ta = t0 + tr, tb2 = t0 + tr + 8;
#pragma unroll
    for (int n = 0; n < 2; n++) {
        int i0 = nh * 16 + n * 8 + cq;
        if (i0 + 1 < VV) {
            *reinterpret_cast<uint32_t*>(zp + (size_t)ta * 26 + i0)  = pack_h2f(acc[n][0], acc[n][1]);
            *reinterpret_cast<uint32_t*>(zp + (size_t)tb2 * 26 + i0) = pack_h2f(acc[n][2], acc[n][3]);
        } else if (i0 < VV) {
            zp[(size_t)ta * 26 + i0]  = __float2half_rn(acc[n][0]);
            zp[(size_t)tb2 * 26 + i0] = __float2half_rn(acc[n][2]);
        }
    }
}

// ---------------- kC_mma: out^T(tv,o) = z^T(tv,c) @ w3(o,c)^T (R15 form, proven) ----------------
__global__ void __launch_bounds__(256) kC_mma(const float* __restrict__ w3,
                                              const float* __restrict__ b3,
                                              float* __restrict__ out) {
    __shared__ __align__(1024) char As[128 * 128];   // 16KB fp16 [tv][c]
    __shared__ __align__(1024) char Bs[64 * 128];    // 8KB  fp16 [o][c]
    __shared__ float bias_s[OUTC];

    int b = blockIdx.y;
    int tv0 = blockIdx.x * 128;
    int tid = threadIdx.x;
    int warp = tid >> 5, lane = tid & 31;

    {
        int tv = tid & 127;
        int tvflat = tv0 + tv;
        int t = tvflat / VV, i = tvflat % VV;
        const __half* zrow = g_zh + (size_t)b * CC * TVP + (size_t)t * 26 + i;
        int mbase = (tid >> 7) * 16;
#pragma unroll 4
        for (int mi = 0; mi < 16; mi++) {
            int m = mbase + mi;
            uint32_t h0 = __half_as_ushort(zrow[(size_t)(2 * m) * TVP]);
            uint32_t h1 = __half_as_ushort(zrow[(size_t)(2 * m + 1) * TVP]);
            uint32_t sw = SMEM_SWIZZLE_128B((uint32_t)tv * 128u + (uint32_t)m * 4u);
            *reinterpret_cast<uint32_t*>(As + sw) = (h1 << 16) | h0;
        }
    }
    for (int e = tid; e < OUTC * CC; e += 256) {
        int o = e >> 6, c = e & 63;
        uint32_t sw = SMEM_SWIZZLE_128B((uint32_t)o * 128u + (uint32_t)c * 2u);
        *reinterpret_cast<__half*>(Bs + sw) = __float2half_rn(w3[e]);
    }
    if (tid < OUTC) bias_s[tid] = b3[tid];
    __syncthreads();

    uint32_t aH = smem_to_u32(As);
    uint32_t bH = smem_to_u32(Bs);

    float acc[8][4];
#pragma unroll
    for (int n = 0; n < 8; n++)
#pragma unroll
        for (int q = 0; q < 4; q++) acc[n][q] = 0.f;

    int tvw = warp * 16;
    uint32_t arow = (uint32_t)(tvw + (lane & 15)) * 128u + (uint32_t)((lane >> 4) & 1) * 16u;
    uint32_t brow = (uint32_t)(((lane >> 4) & 1) * 8 + (lane & 7)) * 128u + (uint32_t)((lane >> 3) & 1) * 16u;

#pragma unroll
    for (int ks = 0; ks < 4; ks++) {
        uint32_t ah[4];
        ldsm_x4(ah, aH + SMEM_SWIZZLE_128B(arow + (uint32_t)ks * 32u));
#pragma unroll
        for (int np = 0; np < 4; np++) {
            uint32_t bh[4];
            ldsm_x4(bh, bH + SMEM_SWIZZLE_128B(brow + (uint32_t)np * 16u * 128u + (uint32_t)ks * 32u));
            mma_16816_f16(acc[2 * np],     ah, bh[0], bh[1]);
            mma_16816_f16(acc[2 * np + 1], ah, bh[2], bh[3]);
        }
    }

    int tr = lane >> 2, cq = (lane & 3) * 2;
    float* ob = out + (size_t)b * OUTC * TV + tv0;
    int tvl = tvw + tr;
#pragma unroll
    for (int n = 0; n < 8; n++) {
        int o0 = n * 8 + cq;
        float bz0 = bias_s[o0], bz1 = bias_s[o0 + 1];
        ob[(size_t)o0 * TV + tvl]            = acc[n][0] + bz0;
        ob[(size_t)(o0 + 1) * TV + tvl]      = acc[n][1] + bz1;
        ob[(size_t)o0 * TV + tvl + 8]        = acc[n][2] + bz0;
        ob[(size_t)(o0 + 1) * TV + tvl + 8]  = acc[n][3] + bz1;
    }
}

extern "C" void kernel_launch(void* const* d_in, const int* in_sizes, int n_in,
                              void* d_out, int out_size) {
    const float* x  = (const float*)d_in[0];
    const float* A  = (const float*)d_in[1];
    const float* w1 = (const float*)d_in[2];
    const float* b1 = (const float*)d_in[3];
    const float* w2 = (const float*)d_in[4];
    const float* b2 = (const float*)d_in[5];
    const float* w3 = (const float*)d_in[6];
    const float* b3 = (const float*)d_in[7];
    const float* w4 = (const float*)d_in[8];
    const float* b4 = (const float*)d_in[9];
    float* out = (float*)d_out;

    kA1<<<dim3(CC, BB), 128>>>(x);
    kA2<<<dim3(RR, BB), 128>>>(w1, b1, w2, b2);
    kB_mma<<<dim3(CC, BB), 512>>>(x, A, w4, b4);
    kC_mma<<<dim3(TV / 128, BB), 256>>>(w3, b3, out);
}